// round 15
// baseline (speedup 1.0000x reference)
#include <cuda_runtime.h>
#include <cuda_bf16.h>
#include <cuda_fp16.h>
#include <cstdint>

#define S_DIM 128
#define R_DIM 256
#define CM    256
#define H_DIM 32
#define CZ    128
#define LN_EPS 1e-5f
#define EPS_N  1e-3f

// GEMM1 operands: [8192, 128] fp16, row-major (m=(i*32+h), k=s)
__device__ __half gAf[8192 * 128];
__device__ __half gBf[8192 * 128];
// w_out in mma-B-fragment order (see R11): 131072 uint32
__device__ uint32_t gWfrag[131072];
__device__ float g_norm[R_DIM * R_DIM];

// ---------------------------------------------------------------------------
__device__ __forceinline__ uint32_t smem_u32(const void* p) {
    uint32_t a;
    asm("{ .reg .u64 t; cvta.to.shared.u64 t, %1; cvt.u32.u64 %0, t; }" : "=r"(a) : "l"(p));
    return a;
}
#define SWZ128(o) ((o) ^ (((o) >> 3) & 0x70))
#define CP_ASYNC16(dst, src) asm volatile("cp.async.cg.shared.global [%0], [%1], 16;" :: "r"(dst), "l"(src))
#define CP_COMMIT()          asm volatile("cp.async.commit_group;" ::: "memory")
#define CP_WAIT(n)           asm volatile("cp.async.wait_group %0;" :: "n"(n) : "memory")

__device__ __forceinline__ void ldsm_x4(uint32_t* r, uint32_t addr) {
    asm volatile("ldmatrix.sync.aligned.m8n8.x4.shared.b16 {%0,%1,%2,%3}, [%4];"
                 : "=r"(r[0]), "=r"(r[1]), "=r"(r[2]), "=r"(r[3]) : "r"(addr));
}
__device__ __forceinline__ void mma_f16(float* d, const uint32_t* a, const uint32_t* b) {
    asm volatile(
        "mma.sync.aligned.m16n8k16.row.col.f32.f16.f16.f32 "
        "{%0,%1,%2,%3}, {%4,%5,%6,%7}, {%8,%9}, {%0,%1,%2,%3};"
        : "+f"(d[0]), "+f"(d[1]), "+f"(d[2]), "+f"(d[3])
        : "r"(a[0]), "r"(a[1]), "r"(a[2]), "r"(a[3]),
          "r"(b[0]), "r"(b[1]));
}
__device__ __forceinline__ uint32_t pack_h2(float lo, float hi) {
    __half2 h;
    h.x = __float2half_rn(lo);
    h.y = __float2half_rn(hi);
    return *(uint32_t*)&h;
}

// ---------------------------------------------------------------------------
// LN + projection kernel, 832 blocks:
//   [0,512):   LN + tensor-core projection (which=blk>>8, i=blk&255)
//              w1/w2 fragments built locally in smem (no prior launch needed)
//   [512,768): norm matrix row i = blk-512
//   [768,832): gWfrag packing, ktg = blk-768 (consumed by fused launch)
// Dynamic smem 90624 B:
//   [0,65536)      xs fp16 [128 s][256 c] swizzled (aliases w-staging)
//   [65536,74240)  ts fp16 [32 h][136 s]
//   [74240,90624)  wfr: 1024 uint4 local W fragments
// ---------------------------------------------------------------------------
__global__ void __launch_bounds__(256) lnproj_kernel(
    const float* __restrict__ m1, const float* __restrict__ mask1,
    const float* __restrict__ ln1w, const float* __restrict__ ln1b,
    const float* __restrict__ w1, const float* __restrict__ b1,
    const float* __restrict__ m2, const float* __restrict__ mask2,
    const float* __restrict__ ln2w, const float* __restrict__ ln2b,
    const float* __restrict__ w2, const float* __restrict__ b2,
    const float* __restrict__ w_out)
{
    extern __shared__ char psm[];
    const int blk = blockIdx.x;
    const int t = threadIdx.x;

    if (blk >= 768) {
        // ---- gWfrag packing: ktg covers k in [ktg*16, ktg*16+16) ----
        const int ktg = blk - 768;
        float* ws = (float*)psm;                  // [16][128]
#pragma unroll
        for (int r = 0; r < 8; r++) {
            int idx = t + r * 256;
            int kk = idx >> 7, n = idx & 127;
            ws[idx] = w_out[(ktg * 16 + kk) * CZ + n];
        }
        __syncthreads();
        const int lane = t & 31, ntp = t >> 5;
        uint32_t pk[4];
#pragma unroll
        for (int r2 = 0; r2 < 4; r2++) {
            int ntsub = r2 >> 1, rr = r2 & 1;
            int kk = (lane & 3) * 2 + rr * 8;
            int n = (ntp * 2 + ntsub) * 8 + (lane >> 2);
            pk[r2] = pack_h2(ws[kk * 128 + n], ws[(kk + 1) * 128 + n]);
        }
        *(uint4*)&gWfrag[ktg * 1024 + t * 4] = *(uint4*)pk;
        return;
    }
    if (blk >= 512) {
        // ---- norm row ----
        const int i = blk - 512, j = t;
        float sum = 0.f;
#pragma unroll 4
        for (int s = 0; s < S_DIM; s++)
            sum += mask1[s * R_DIM + i] * mask2[s * R_DIM + j];
        g_norm[i * R_DIM + j] = sum + EPS_N;
        return;
    }

    // ---- LN + tensor-core projection ----
    const int which = blk >> 8;
    const int i = blk & 255;
    const float* m    = which ? m2 : m1;
    const float* mask = which ? mask2 : mask1;
    const float* lnw  = which ? ln2w : ln1w;
    const float* lnb  = which ? ln2b : ln1b;
    const float* wsrc = which ? w2 : w1;
    const float* bias = which ? b2 : b1;

    __half* xs = (__half*)psm;                 // [128][256] swizzled, 512 B rows
    __half* ts = (__half*)(psm + 65536);       // [32][136]
    char*  wfr = psm + 74240;                  // 1024 uint4
    const int w = t >> 5, lane = t & 31;
    const int quad = lane >> 3, r8 = lane & 7;

    // ---- stage w coalesced into smem (region later reused by xs) ----
    {
        float* ws = (float*)psm;               // [256][32] = 32 KB
#pragma unroll
        for (int r = 0; r < 32; r++)
            ws[t + r * 256] = wsrc[t + r * 256];
        __syncthreads();
        // pack local W fragments: u2 = kt*256 + ntp*128 + lane*4 + r2
        const int pl = t & 31, pntp = (t >> 5) & 1, ktb = t >> 6;   // ktb 0..3
#pragma unroll
        for (int k4 = 0; k4 < 4; k4++) {
            int kt = ktb * 4 + k4;
            uint32_t pk[4];
#pragma unroll
            for (int r2 = 0; r2 < 4; r2++) {
                int ntsub = r2 >> 1, rr = r2 & 1;
                int k = kt * 16 + (pl & 3) * 2 + rr * 8;
                int n = (pntp * 2 + ntsub) * 8 + (pl >> 2);
                pk[r2] = pack_h2(ws[k * H_DIM + n], ws[(k + 1) * H_DIM + n]);
            }
            *(uint4*)(wfr + ((kt * 2 + pntp) * 32 + pl) * 16) = *(uint4*)pk;
        }
        __syncthreads();   // ws fully consumed; xs may overwrite
    }

    const int c0 = lane * 8;
    float4 lw0 = *(const float4*)(lnw + c0);
    float4 lw1 = *(const float4*)(lnw + c0 + 4);
    float4 lb0 = *(const float4*)(lnb + c0);
    float4 lb1 = *(const float4*)(lnb + c0 + 4);
#pragma unroll 4
    for (int r = 0; r < 16; r++) {
        int s = w * 16 + r;
        const float* row = m + ((size_t)s * 256 + i) * CM;
        float4 v0 = *(const float4*)(row + c0);
        float4 v1 = *(const float4*)(row + c0 + 4);
        float sum = v0.x + v0.y + v0.z + v0.w + v1.x + v1.y + v1.z + v1.w;
#pragma unroll
        for (int o = 16; o; o >>= 1) sum += __shfl_xor_sync(0xffffffffu, sum, o);
        float mu = sum * (1.f / CM);
        float vs = (v0.x-mu)*(v0.x-mu) + (v0.y-mu)*(v0.y-mu) + (v0.z-mu)*(v0.z-mu)
                 + (v0.w-mu)*(v0.w-mu) + (v1.x-mu)*(v1.x-mu) + (v1.y-mu)*(v1.y-mu)
                 + (v1.z-mu)*(v1.z-mu) + (v1.w-mu)*(v1.w-mu);
#pragma unroll
        for (int o = 16; o; o >>= 1) vs += __shfl_xor_sync(0xffffffffu, vs, o);
        float rstd = rsqrtf(vs * (1.f / CM) + LN_EPS);
        uint4 pk;
        pk.x = pack_h2((v0.x - mu) * rstd * lw0.x + lb0.x,
                       (v0.y - mu) * rstd * lw0.y + lb0.y);
        pk.y = pack_h2((v0.z - mu) * rstd * lw0.z + lb0.z,
                       (v0.w - mu) * rstd * lw0.w + lb0.w);
        pk.z = pack_h2((v1.x - mu) * rstd * lw1.x + lb1.x,
                       (v1.y - mu) * rstd * lw1.y + lb1.y);
        pk.w = pack_h2((v1.z - mu) * rstd * lw1.z + lb1.z,
                       (v1.w - mu) * rstd * lw1.w + lb1.w);
        uint32_t off = (uint32_t)(s * 512 + ((lane * 16) ^ ((s & 7) << 4)));
        *(uint4*)((char*)xs + off) = pk;
    }
    __syncthreads();

    uint32_t sbx = smem_u32(xs);
    float acc[4][4];
#pragma unroll
    for (int a = 0; a < 4; a++)
#pragma unroll
        for (int b = 0; b < 4; b++) acc[a][b] = 0.f;

#pragma unroll
    for (int kt = 0; kt < 16; kt++) {
        int arow = w * 16 + (quad & 1) * 8 + r8;
        uint32_t akb = (uint32_t)(kt * 32 + (quad >> 1) * 16);
        uint32_t aoff = (uint32_t)(arow * 512) + (akb ^ ((uint32_t)(arow & 7) << 4));
        uint32_t a4[4];
        ldsm_x4(a4, sbx + aoff);
        uint4 wv0 = *(const uint4*)(wfr + ((kt * 2 + 0) * 32 + lane) * 16);
        uint4 wv1 = *(const uint4*)(wfr + ((kt * 2 + 1) * 32 + lane) * 16);
        uint32_t b0[2] = {wv0.x, wv0.y}, b1r[2] = {wv0.z, wv0.w};
        uint32_t b2r[2] = {wv1.x, wv1.y}, b3[2] = {wv1.z, wv1.w};
        mma_f16(acc[0], a4, b0);
        mma_f16(acc[1], a4, b1r);
        mma_f16(acc[2], a4, b2r);
        mma_f16(acc[3], a4, b3);
    }

    {
        float mk0 = mask[(w * 16 + (lane >> 2)) * 256 + i];
        float mk1 = mask[(w * 16 + (lane >> 2) + 8) * 256 + i];
#pragma unroll
        for (int n8 = 0; n8 < 4; n8++) {
            int h = n8 * 8 + (lane & 3) * 2;
            float bh0 = __ldg(bias + h), bh1 = __ldg(bias + h + 1);
#pragma unroll
            for (int hh = 0; hh < 2; hh++) {
                int s = w * 16 + (lane >> 2) + hh * 8;
                float mk = hh ? mk1 : mk0;
                ts[h * 136 + s]       = __float2half_rn((acc[n8][hh * 2 + 0] + bh0) * mk);
                ts[(h + 1) * 136 + s] = __float2half_rn((acc[n8][hh * 2 + 1] + bh1) * mk);
            }
        }
    }
    __syncthreads();

    {
        int h = t >> 3, g0 = t & 7;
        __half* dst = (which ? gBf : gAf);
#pragma unroll
        for (int r = 0; r < 2; r++) {
            int grp = g0 + r * 8;
            uint4 v = *(uint4*)((char*)ts + h * 272 + grp * 16);
            *(uint4*)&dst[((size_t)i * 32 + h) * 128 + grp * 8] = v;
        }
    }
}

// ---------------------------------------------------------------------------
// Mainloop blocks (fp16). K-chunk = 64 elems, SW128 tiles. 32 KB per chunk.
// ---------------------------------------------------------------------------
__device__ __forceinline__ void load_chunk_async(
    uint32_t sbuf, int m0, int n0, int k0, int t)
{
#pragma unroll
    for (int it = 0; it < 8; it++) {
        int id = it * 256 + t;
        int tile = id >> 10;
        int rem = id & 1023;
        int r = rem >> 3;
        int c8 = (rem & 7) * 8;
        const __half* src = (tile == 0)
            ? gAf + (size_t)(m0 + r) * 128 + k0 + c8
            : gBf + (size_t)(n0 + r) * 128 + k0 + c8;
        uint32_t off = (uint32_t)(r * 128 + c8 * 2);
        CP_ASYNC16(sbuf + tile * 16384 + SWZ128(off), src);
    }
}

__device__ __forceinline__ void compute_chunk(
    uint32_t sbuf, int wm0, int wn0, int lane, float (*acc)[4][4])
{
    const int quad = lane >> 3, r8 = lane & 7;
#pragma unroll
    for (int ks = 0; ks < 4; ks++) {
        const int kb = ks * 32;
        uint32_t a4[4][4];
#pragma unroll
        for (int mf = 0; mf < 4; mf++) {
            int row = wm0 + mf * 16 + (quad & 1) * 8 + r8;
            int kbyte = kb + (quad >> 1) * 16;
            ldsm_x4(a4[mf], sbuf + SWZ128((uint32_t)(row * 128 + kbyte)));
        }
        uint32_t b4[4][2];
#pragma unroll
        for (int nb = 0; nb < 2; nb++) {
            int row = wn0 + nb * 16 + (quad >> 1) * 8 + r8;
            int kbyte = kb + (quad & 1) * 16;
            uint32_t r4[4];
            ldsm_x4(r4, sbuf + 16384 + SWZ128((uint32_t)(row * 128 + kbyte)));
            b4[nb * 2][0] = r4[0]; b4[nb * 2][1] = r4[1];
            b4[nb * 2 + 1][0] = r4[2]; b4[nb * 2 + 1][1] = r4[3];
        }
#pragma unroll
        for (int mf = 0; mf < 4; mf++)
#pragma unroll
            for (int nf = 0; nf < 4; nf++)
                mma_f16(acc[mf][nf], a4[mf], b4[nf]);
    }
}

// ---------------------------------------------------------------------------
// Fused kernel. Dynamic smem 100352 B. W loads batched per kt (MLP=8).
// ---------------------------------------------------------------------------
__global__ void __launch_bounds__(256, 2) fused_kernel(
    const float* __restrict__ b_out, float* __restrict__ out)
{
    extern __shared__ char dsm[];
    const int t = threadIdx.x, wid = t >> 5, lane = t & 31;
    const int bi = blockIdx.y, bj = blockIdx.x;
    const int m0 = bi * 128, n0 = bj * 128;
    const int wm0 = (wid >> 2) * 64, wn0 = (wid & 3) * 32;
    const int quad = lane >> 3, r8 = lane & 7;
    uint32_t sb = smem_u32(dsm);

    float acc[4][4][4];
#pragma unroll
    for (int a = 0; a < 4; a++)
#pragma unroll
        for (int b = 0; b < 4; b++)
#pragma unroll
            for (int c = 0; c < 4; c++) acc[a][b][c] = 0.f;

    load_chunk_async(sb, m0, n0, 0, t);
    load_chunk_async(sb + 32768, m0, n0, 64, t);
    CP_COMMIT();
    CP_WAIT(0);
    __syncthreads();
    compute_chunk(sb, wm0, wn0, lane, acc);
    compute_chunk(sb + 32768, wm0, wn0, lane, acc);
    __syncthreads();

#pragma unroll
    for (int mf = 0; mf < 4; mf++)
#pragma unroll
        for (int nf = 0; nf < 4; nf++)
#pragma unroll
            for (int half = 0; half < 2; half++) {
                int gm = wm0 + mf * 16 + (lane >> 2) + half * 8;
                int gn = wn0 + nf * 8 + (lane & 3) * 2;
                int p = ((gm >> 5) << 2) | (gn >> 5);
                int k = ((gm & 31) << 5) | (gn & 31);
                __half2 hp;
                hp.x = __float2half_rn(acc[mf][nf][half * 2 + 0]);
                hp.y = __float2half_rn(acc[mf][nf][half * 2 + 1]);
                uint32_t off = (uint32_t)(p * 2048 + ((k * 2) ^ ((p & 7) << 4)));
                *(__half2*)(dsm + off) = hp;
            }
    __syncthreads();

    float zacc[16][4];
#pragma unroll
    for (int a = 0; a < 16; a++)
#pragma unroll
        for (int b = 0; b < 4; b++) zacc[a][b] = 0.f;

#pragma unroll
    for (int kt = 0; kt < 8; kt++) {
        int arow = (quad & 1) * 8 + r8;
        uint32_t akb = (uint32_t)(wid * 256 + kt * 32 + (quad >> 1) * 16);
        uint32_t aoff = (uint32_t)(arow * 2048) + (akb ^ ((uint32_t)(arow & 7) << 4));
        uint32_t ah[4];
        ldsm_x4(ah, sb + aoff);
        uint4 bv[8];
#pragma unroll
        for (int ntp = 0; ntp < 8; ntp++)
            bv[ntp] = __ldg(reinterpret_cast<const uint4*>(gWfrag)
                            + ((wid * 8 + kt) * 8 + ntp) * 32 + lane);
#pragma unroll
        for (int ntp = 0; ntp < 8; ntp++) {
            uint32_t b0[2] = {bv[ntp].x, bv[ntp].y}, b1[2] = {bv[ntp].z, bv[ntp].w};
            mma_f16(zacc[ntp * 2],     ah, b0);
            mma_f16(zacc[ntp * 2 + 1], ah, b1);
        }
    }

    {
        char* red = dsm + 32768 + wid * 8448;
#pragma unroll
        for (int nf = 0; nf < 16; nf++)
#pragma unroll
            for (int hh = 0; hh < 2; hh++) {
                int p = (lane >> 2) + hh * 8;
                int z = nf * 8 + (lane & 3) * 2;
                float2 v;
                v.x = zacc[nf][hh * 2 + 0];
                v.y = zacc[nf][hh * 2 + 1];
                *(float2*)(red + p * 528 + z * 4) = v;
            }
    }
    __syncthreads();

#pragma unroll
    for (int g2 = 0; g2 < 2; g2++) {
        int cell = t + g2 * 256;
        int p = cell >> 5;
        int z = (cell & 31) * 4;
        float4 s = {0.f, 0.f, 0.f, 0.f};
#pragma unroll
        for (int w = 0; w < 8; w++) {
            float4 v = *(float4*)(dsm + 32768 + w * 8448 + p * 528 + z * 4);
            s.x += v.x; s.y += v.y; s.z += v.z; s.w += v.w;
        }
        int i = bi * 4 + (p >> 2), j = bj * 4 + (p & 3);
        float invn = 1.f / g_norm[i * R_DIM + j];
        float4 bo = __ldg((const float4*)(b_out + z));
        float4 o;
        o.x = (s.x + bo.x) * invn;
        o.y = (s.y + bo.y) * invn;
        o.z = (s.z + bo.z) * invn;
        o.w = (s.w + bo.w) * invn;
        *(float4*)(out + ((size_t)i * R_DIM + j) * CZ + z) = o;
    }
}

// ---------------------------------------------------------------------------
extern "C" void kernel_launch(void* const* d_in, const int* in_sizes, int n_in,
                              void* d_out, int out_size)
{
    const float* m_1    = (const float*)d_in[0];
    const float* m_2    = (const float*)d_in[1];
    const float* mask_1 = (const float*)d_in[2];
    const float* mask_2 = (const float*)d_in[3];
    const float* ln1_w  = (const float*)d_in[4];
    const float* ln1_b  = (const float*)d_in[5];
    const float* ln2_w  = (const float*)d_in[6];
    const float* ln2_b  = (const float*)d_in[7];
    const float* w1     = (const float*)d_in[8];
    const float* b1     = (const float*)d_in[9];
    const float* w2     = (const float*)d_in[10];
    const float* b2     = (const float*)d_in[11];
    const float* w_out  = (const float*)d_in[12];
    const float* b_out  = (const float*)d_in[13];
    float* out = (float*)d_out;

    cudaFuncSetAttribute(lnproj_kernel,
                         cudaFuncAttributeMaxDynamicSharedMemorySize, 90624);
    cudaFuncSetAttribute(fused_kernel,
                         cudaFuncAttributeMaxDynamicSharedMemorySize, 100352);

    lnproj_kernel<<<832, 256, 90624>>>(m_1, mask_1, ln1_w, ln1_b, w1, b1,
                                       m_2, mask_2, ln2_w, ln2_b, w2, b2, w_out);
    fused_kernel<<<dim3(64, 64), 256, 100352>>>(b_out, out);
}

// round 16
// speedup vs baseline: 1.0741x; 1.0741x over previous
#include <cuda_runtime.h>
#include <cuda_bf16.h>
#include <cuda_fp16.h>
#include <cstdint>

#define S_DIM 128
#define R_DIM 256
#define CM    256
#define H_DIM 32
#define CZ    128
#define LN_EPS 1e-5f
#define EPS_N  1e-3f

// GEMM1 operands: [8192, 128] fp16, row-major (m=(i*32+h), k=s)
__device__ __half gAf[8192 * 128];
__device__ __half gBf[8192 * 128];
// w_out in mma-B-fragment order (see R11): 131072 uint32
__device__ uint32_t gWfrag[131072];
// w1/w2 in mma-B-fragment order: u = which*4096 + kt*256 + ntp*128 + lane*4 + r2
__device__ uint32_t gW12[8192];
__device__ float g_norm[R_DIM * R_DIM];

// ---------------------------------------------------------------------------
__device__ __forceinline__ uint32_t smem_u32(const void* p) {
    uint32_t a;
    asm("{ .reg .u64 t; cvta.to.shared.u64 t, %1; cvt.u32.u64 %0, t; }" : "=r"(a) : "l"(p));
    return a;
}
#define SWZ128(o) ((o) ^ (((o) >> 3) & 0x70))
#define CP_ASYNC16(dst, src) asm volatile("cp.async.cg.shared.global [%0], [%1], 16;" :: "r"(dst), "l"(src))
#define CP_COMMIT()          asm volatile("cp.async.commit_group;" ::: "memory")
#define CP_WAIT(n)           asm volatile("cp.async.wait_group %0;" :: "n"(n) : "memory")

__device__ __forceinline__ void ldsm_x4(uint32_t* r, uint32_t addr) {
    asm volatile("ldmatrix.sync.aligned.m8n8.x4.shared.b16 {%0,%1,%2,%3}, [%4];"
                 : "=r"(r[0]), "=r"(r[1]), "=r"(r[2]), "=r"(r[3]) : "r"(addr));
}
__device__ __forceinline__ void mma_f16(float* d, const uint32_t* a, const uint32_t* b) {
    asm volatile(
        "mma.sync.aligned.m16n8k16.row.col.f32.f16.f16.f32 "
        "{%0,%1,%2,%3}, {%4,%5,%6,%7}, {%8,%9}, {%0,%1,%2,%3};"
        : "+f"(d[0]), "+f"(d[1]), "+f"(d[2]), "+f"(d[3])
        : "r"(a[0]), "r"(a[1]), "r"(a[2]), "r"(a[3]),
          "r"(b[0]), "r"(b[1]));
}
__device__ __forceinline__ uint32_t pack_h2(float lo, float hi) {
    __half2 h;
    h.x = __float2half_rn(lo);
    h.y = __float2half_rn(hi);
    return *(uint32_t*)&h;
}

// ---------------------------------------------------------------------------
// Prep kernel (runs FIRST): gW12 packing only. 2 blocks (which = blockIdx.x).
// ---------------------------------------------------------------------------
__global__ void __launch_bounds__(256) prep_kernel(
    const float* __restrict__ w1, const float* __restrict__ w2)
{
    __shared__ float ws[CM * H_DIM];    // 32 KB
    const int which = blockIdx.x;
    const int t = threadIdx.x;
    const float* wsrc = which ? w2 : w1;

#pragma unroll
    for (int r = 0; r < 32; r++)
        ws[t + r * 256] = wsrc[t + r * 256];
    __syncthreads();

#pragma unroll
    for (int r = 0; r < 16; r++) {
        int u2 = r * 256 + t;
        int r2 = u2 & 3;
        int lane = (u2 >> 2) & 31;
        int ntp = (u2 >> 7) & 1;
        int kt = u2 >> 8;
        int ntsub = r2 >> 1, rr = r2 & 1;
        int k = kt * 16 + (lane & 3) * 2 + rr * 8;
        int n = (ntp * 2 + ntsub) * 8 + (lane >> 2);
        unsigned short lo = __half_as_ushort(__float2half_rn(ws[k * H_DIM + n]));
        unsigned short hi = __half_as_ushort(__float2half_rn(ws[(k + 1) * H_DIM + n]));
        gW12[which * 4096 + u2] = (uint32_t)lo | ((uint32_t)hi << 16);
    }
}

// ---------------------------------------------------------------------------
// LN + projection kernel, 832 blocks (R14 version):
//   [0,512):   LN + tensor-core projection (which=blk>>8, i=blk&255)
//   [512,768): norm matrix row i = blk-512
//   [768,832): gWfrag packing, ktg = blk-768
// Dynamic smem 74240 B.
// ---------------------------------------------------------------------------
__global__ void __launch_bounds__(256) lnproj_kernel(
    const float* __restrict__ m1, const float* __restrict__ mask1,
    const float* __restrict__ ln1w, const float* __restrict__ ln1b,
    const float* __restrict__ b1,
    const float* __restrict__ m2, const float* __restrict__ mask2,
    const float* __restrict__ ln2w, const float* __restrict__ ln2b,
    const float* __restrict__ b2,
    const float* __restrict__ w_out)
{
    extern __shared__ char psm[];
    const int blk = blockIdx.x;
    const int t = threadIdx.x;

    if (blk >= 768) {
        const int ktg = blk - 768;
        float* ws = (float*)psm;                  // [16][128]
#pragma unroll
        for (int r = 0; r < 8; r++) {
            int idx = t + r * 256;
            int kk = idx >> 7, n = idx & 127;
            ws[idx] = w_out[(ktg * 16 + kk) * CZ + n];
        }
        __syncthreads();
        const int lane = t & 31, ntp = t >> 5;
        uint32_t pk[4];
#pragma unroll
        for (int r2 = 0; r2 < 4; r2++) {
            int ntsub = r2 >> 1, rr = r2 & 1;
            int kk = (lane & 3) * 2 + rr * 8;
            int n = (ntp * 2 + ntsub) * 8 + (lane >> 2);
            pk[r2] = pack_h2(ws[kk * 128 + n], ws[(kk + 1) * 128 + n]);
        }
        *(uint4*)&gWfrag[ktg * 1024 + t * 4] = *(uint4*)pk;
        return;
    }
    if (blk >= 512) {
        const int i = blk - 512, j = t;
        float sum = 0.f;
#pragma unroll 4
        for (int s = 0; s < S_DIM; s++)
            sum += mask1[s * R_DIM + i] * mask2[s * R_DIM + j];
        g_norm[i * R_DIM + j] = sum + EPS_N;
        return;
    }

    const int which = blk >> 8;
    const int i = blk & 255;
    const float* m    = which ? m2 : m1;
    const float* mask = which ? mask2 : mask1;
    const float* lnw  = which ? ln2w : ln1w;
    const float* lnb  = which ? ln2b : ln1b;
    const float* bias = which ? b2 : b1;

    __half* xs = (__half*)psm;                 // [128][256] swizzled, 512 B rows
    __half* ts = (__half*)(psm + 65536);       // [32][136]
    const int w = t >> 5, lane = t & 31;
    const int quad = lane >> 3, r8 = lane & 7;

    const int c0 = lane * 8;
    float4 lw0 = *(const float4*)(lnw + c0);
    float4 lw1 = *(const float4*)(lnw + c0 + 4);
    float4 lb0 = *(const float4*)(lnb + c0);
    float4 lb1 = *(const float4*)(lnb + c0 + 4);
#pragma unroll 4
    for (int r = 0; r < 16; r++) {
        int s = w * 16 + r;
        const float* row = m + ((size_t)s * 256 + i) * CM;
        float4 v0 = *(const float4*)(row + c0);
        float4 v1 = *(const float4*)(row + c0 + 4);
        float sum = v0.x + v0.y + v0.z + v0.w + v1.x + v1.y + v1.z + v1.w;
#pragma unroll
        for (int o = 16; o; o >>= 1) sum += __shfl_xor_sync(0xffffffffu, sum, o);
        float mu = sum * (1.f / CM);
        float vs = (v0.x-mu)*(v0.x-mu) + (v0.y-mu)*(v0.y-mu) + (v0.z-mu)*(v0.z-mu)
                 + (v0.w-mu)*(v0.w-mu) + (v1.x-mu)*(v1.x-mu) + (v1.y-mu)*(v1.y-mu)
                 + (v1.z-mu)*(v1.z-mu) + (v1.w-mu)*(v1.w-mu);
#pragma unroll
        for (int o = 16; o; o >>= 1) vs += __shfl_xor_sync(0xffffffffu, vs, o);
        float rstd = rsqrtf(vs * (1.f / CM) + LN_EPS);
        uint4 pk;
        pk.x = pack_h2((v0.x - mu) * rstd * lw0.x + lb0.x,
                       (v0.y - mu) * rstd * lw0.y + lb0.y);
        pk.y = pack_h2((v0.z - mu) * rstd * lw0.z + lb0.z,
                       (v0.w - mu) * rstd * lw0.w + lb0.w);
        pk.z = pack_h2((v1.x - mu) * rstd * lw1.x + lb1.x,
                       (v1.y - mu) * rstd * lw1.y + lb1.y);
        pk.w = pack_h2((v1.z - mu) * rstd * lw1.z + lb1.z,
                       (v1.w - mu) * rstd * lw1.w + lb1.w);
        uint32_t off = (uint32_t)(s * 512 + ((lane * 16) ^ ((s & 7) << 4)));
        *(uint4*)((char*)xs + off) = pk;
    }
    __syncthreads();

    uint32_t sbx = smem_u32(xs);
    float acc[4][4];
#pragma unroll
    for (int a = 0; a < 4; a++)
#pragma unroll
        for (int b = 0; b < 4; b++) acc[a][b] = 0.f;

#pragma unroll
    for (int kt = 0; kt < 16; kt++) {
        int arow = w * 16 + (quad & 1) * 8 + r8;
        uint32_t akb = (uint32_t)(kt * 32 + (quad >> 1) * 16);
        uint32_t aoff = (uint32_t)(arow * 512) + (akb ^ ((uint32_t)(arow & 7) << 4));
        uint32_t a4[4];
        ldsm_x4(a4, sbx + aoff);
        uint4 wv0 = __ldg((const uint4*)gW12 + (which * 32 + kt * 2 + 0) * 32 + lane);
        uint4 wv1 = __ldg((const uint4*)gW12 + (which * 32 + kt * 2 + 1) * 32 + lane);
        uint32_t b0[2] = {wv0.x, wv0.y}, b1r[2] = {wv0.z, wv0.w};
        uint32_t b2r[2] = {wv1.x, wv1.y}, b3[2] = {wv1.z, wv1.w};
        mma_f16(acc[0], a4, b0);
        mma_f16(acc[1], a4, b1r);
        mma_f16(acc[2], a4, b2r);
        mma_f16(acc[3], a4, b3);
    }

    {
        float mk0 = mask[(w * 16 + (lane >> 2)) * 256 + i];
        float mk1 = mask[(w * 16 + (lane >> 2) + 8) * 256 + i];
#pragma unroll
        for (int n8 = 0; n8 < 4; n8++) {
            int h = n8 * 8 + (lane & 3) * 2;
            float bh0 = __ldg(bias + h), bh1 = __ldg(bias + h + 1);
#pragma unroll
            for (int hh = 0; hh < 2; hh++) {
                int s = w * 16 + (lane >> 2) + hh * 8;
                float mk = hh ? mk1 : mk0;
                ts[h * 136 + s]       = __float2half_rn((acc[n8][hh * 2 + 0] + bh0) * mk);
                ts[(h + 1) * 136 + s] = __float2half_rn((acc[n8][hh * 2 + 1] + bh1) * mk);
            }
        }
    }
    __syncthreads();

    {
        int h = t >> 3, g0 = t & 7;
        __half* dst = (which ? gBf : gAf);
#pragma unroll
        for (int r = 0; r < 2; r++) {
            int grp = g0 + r * 8;
            uint4 v = *(uint4*)((char*)ts + h * 272 + grp * 16);
            *(uint4*)&dst[((size_t)i * 32 + h) * 128 + grp * 8] = v;
        }
    }
}

// ---------------------------------------------------------------------------
// Mainloop blocks (fp16). K-chunk = 64 elems, SW128 tiles. 32 KB per chunk.
// ---------------------------------------------------------------------------
__device__ __forceinline__ void load_chunk_async(
    uint32_t sbuf, int m0, int n0, int k0, int t)
{
#pragma unroll
    for (int it = 0; it < 8; it++) {
        int id = it * 256 + t;
        int tile = id >> 10;
        int rem = id & 1023;
        int r = rem >> 3;
        int c8 = (rem & 7) * 8;
        const __half* src = (tile == 0)
            ? gAf + (size_t)(m0 + r) * 128 + k0 + c8
            : gBf + (size_t)(n0 + r) * 128 + k0 + c8;
        uint32_t off = (uint32_t)(r * 128 + c8 * 2);
        CP_ASYNC16(sbuf + tile * 16384 + SWZ128(off), src);
    }
}

__device__ __forceinline__ void compute_chunk(
    uint32_t sbuf, int wm0, int wn0, int lane, float (*acc)[4][4])
{
    const int quad = lane >> 3, r8 = lane & 7;
#pragma unroll
    for (int ks = 0; ks < 4; ks++) {
        const int kb = ks * 32;
        uint32_t a4[4][4];
#pragma unroll
        for (int mf = 0; mf < 4; mf++) {
            int row = wm0 + mf * 16 + (quad & 1) * 8 + r8;
            int kbyte = kb + (quad >> 1) * 16;
            ldsm_x4(a4[mf], sbuf + SWZ128((uint32_t)(row * 128 + kbyte)));
        }
        uint32_t b4[4][2];
#pragma unroll
        for (int nb = 0; nb < 2; nb++) {
            int row = wn0 + nb * 16 + (quad >> 1) * 8 + r8;
            int kbyte = kb + (quad & 1) * 16;
            uint32_t r4[4];
            ldsm_x4(r4, sbuf + 16384 + SWZ128((uint32_t)(row * 128 + kbyte)));
            b4[nb * 2][0] = r4[0]; b4[nb * 2][1] = r4[1];
            b4[nb * 2 + 1][0] = r4[2]; b4[nb * 2 + 1][1] = r4[3];
        }
#pragma unroll
        for (int mf = 0; mf < 4; mf++)
#pragma unroll
            for (int nf = 0; nf < 4; nf++)
                mma_f16(acc[mf][nf], a4[mf], b4[nf]);
    }
}

// ---------------------------------------------------------------------------
// Fused kernel. Dynamic smem 100352 B:
//   mainloop: chunk0 @0 (32 KB), chunk1 @32768 (32 KB)
//   epilogue: O fp16 [16 p][1024 k] @0 (32 KB)
//             reduction slab @32768: [4 kp][16 p][132 floats] (33792 B)
// Epilogue partition: warp = (kp = wid&3, np = wid>>2).
//   kp owns k in [kp*256,(kp+1)*256); np owns z in [np*64,(np+1)*64).
//   4 partials per (p,z) -> reduction traffic halved vs 8-way K split.
// ---------------------------------------------------------------------------
__global__ void __launch_bounds__(256, 2) fused_kernel(
    const float* __restrict__ b_out, float* __restrict__ out)
{
    extern __shared__ char dsm[];
    const int t = threadIdx.x, wid = t >> 5, lane = t & 31;
    const int bi = blockIdx.y, bj = blockIdx.x;
    const int m0 = bi * 128, n0 = bj * 128;
    const int wm0 = (wid >> 2) * 64, wn0 = (wid & 3) * 32;
    const int quad = lane >> 3, r8 = lane & 7;
    uint32_t sb = smem_u32(dsm);

    float acc[4][4][4];
#pragma unroll
    for (int a = 0; a < 4; a++)
#pragma unroll
        for (int b = 0; b < 4; b++)
#pragma unroll
            for (int c = 0; c < 4; c++) acc[a][b][c] = 0.f;

    load_chunk_async(sb, m0, n0, 0, t);
    load_chunk_async(sb + 32768, m0, n0, 64, t);
    CP_COMMIT();
    CP_WAIT(0);
    __syncthreads();
    compute_chunk(sb, wm0, wn0, lane, acc);
    compute_chunk(sb + 32768, wm0, wn0, lane, acc);
    __syncthreads();

    // ---- stage outer tile to smem fp16: [p=16][k=1024] ----
#pragma unroll
    for (int mf = 0; mf < 4; mf++)
#pragma unroll
        for (int nf = 0; nf < 4; nf++)
#pragma unroll
            for (int half = 0; half < 2; half++) {
                int gm = wm0 + mf * 16 + (lane >> 2) + half * 8;
                int gn = wn0 + nf * 8 + (lane & 3) * 2;
                int p = ((gm >> 5) << 2) | (gn >> 5);
                int k = ((gm & 31) << 5) | (gn & 31);
                __half2 hp;
                hp.x = __float2half_rn(acc[mf][nf][half * 2 + 0]);
                hp.y = __float2half_rn(acc[mf][nf][half * 2 + 1]);
                uint32_t off = (uint32_t)(p * 2048 + ((k * 2) ^ ((p & 7) << 4)));
                *(__half2*)(dsm + off) = hp;
            }
    __syncthreads();

    // ---- projection: warp (kp, np); k-slice 256, z-half 64 ----
    const int kp = wid & 3, np = wid >> 2;
    float zacc[8][4];
#pragma unroll
    for (int a = 0; a < 8; a++)
#pragma unroll
        for (int b = 0; b < 4; b++) zacc[a][b] = 0.f;

#pragma unroll
    for (int kt = 0; kt < 16; kt++) {
        int arow = (quad & 1) * 8 + r8;
        uint32_t akb = (uint32_t)(kp * 512 + kt * 32 + (quad >> 1) * 16);
        uint32_t aoff = (uint32_t)(arow * 2048) + (akb ^ ((uint32_t)(arow & 7) << 4));
        uint32_t ah[4];
        ldsm_x4(ah, sb + aoff);
        const int ktg = kp * 16 + kt;
        uint4 bv[4];
#pragma unroll
        for (int nl = 0; nl < 4; nl++)
            bv[nl] = __ldg(reinterpret_cast<const uint4*>(gWfrag)
                           + ((ktg * 8 + (np * 4 + nl)) * 32) + lane);
#pragma unroll
        for (int nl = 0; nl < 4; nl++) {
            uint32_t b0[2] = {bv[nl].x, bv[nl].y}, b1[2] = {bv[nl].z, bv[nl].w};
            mma_f16(zacc[nl * 2],     ah, b0);
            mma_f16(zacc[nl * 2 + 1], ah, b1);
        }
    }

    // ---- store partials: red[kp][p][132 floats]; np halves write disjoint z ----
    {
        char* red = dsm + 32768 + kp * 8448;
#pragma unroll
        for (int nf = 0; nf < 8; nf++)
#pragma unroll
            for (int hh = 0; hh < 2; hh++) {
                int p = (lane >> 2) + hh * 8;
                int z = np * 64 + nf * 8 + (lane & 3) * 2;
                float2 v;
                v.x = zacc[nf][hh * 2 + 0];
                v.y = zacc[nf][hh * 2 + 1];
                *(float2*)(red + p * 528 + z * 4) = v;
            }
    }
    __syncthreads();

    // ---- sum 4 partials, bias, 1/norm, store ----
#pragma unroll
    for (int g2 = 0; g2 < 2; g2++) {
        int cell = t + g2 * 256;
        int p = cell >> 5;
        int z = (cell & 31) * 4;
        float4 s = {0.f, 0.f, 0.f, 0.f};
#pragma unroll
        for (int w = 0; w < 4; w++) {
            float4 v = *(float4*)(dsm + 32768 + w * 8448 + p * 528 + z * 4);
            s.x += v.x; s.y += v.y; s.z += v.z; s.w += v.w;
        }
        int i = bi * 4 + (p >> 2), j = bj * 4 + (p & 3);
        float invn = 1.f / g_norm[i * R_DIM + j];
        float4 bo = __ldg((const float4*)(b_out + z));
        float4 o;
        o.x = (s.x + bo.x) * invn;
        o.y = (s.y + bo.y) * invn;
        o.z = (s.z + bo.z) * invn;
        o.w = (s.w + bo.w) * invn;
        *(float4*)(out + ((size_t)i * R_DIM + j) * CZ + z) = o;
    }
}

// ---------------------------------------------------------------------------
extern "C" void kernel_launch(void* const* d_in, const int* in_sizes, int n_in,
                              void* d_out, int out_size)
{
    const float* m_1    = (const float*)d_in[0];
    const float* m_2    = (const float*)d_in[1];
    const float* mask_1 = (const float*)d_in[2];
    const float* mask_2 = (const float*)d_in[3];
    const float* ln1_w  = (const float*)d_in[4];
    const float* ln1_b  = (const float*)d_in[5];
    const float* ln2_w  = (const float*)d_in[6];
    const float* ln2_b  = (const float*)d_in[7];
    const float* w1     = (const float*)d_in[8];
    const float* b1     = (const float*)d_in[9];
    const float* w2     = (const float*)d_in[10];
    const float* b2     = (const float*)d_in[11];
    const float* w_out  = (const float*)d_in[12];
    const float* b_out  = (const float*)d_in[13];
    float* out = (float*)d_out;

    cudaFuncSetAttribute(lnproj_kernel,
                         cudaFuncAttributeMaxDynamicSharedMemorySize, 74240);
    cudaFuncSetAttribute(fused_kernel,
                         cudaFuncAttributeMaxDynamicSharedMemorySize, 100352);

    prep_kernel<<<2, 256>>>(w1, w2);
    lnproj_kernel<<<832, 256, 74240>>>(m_1, mask_1, ln1_w, ln1_b, b1,
                                       m_2, mask_2, ln2_w, ln2_b, b2, w_out);
    fused_kernel<<<dim3(64, 64), 256, 100352>>>(b_out, out);
}

// round 17
// speedup vs baseline: 1.1375x; 1.0590x over previous
#include <cuda_runtime.h>
#include <cuda_bf16.h>
#include <cuda_fp16.h>
#include <cstdint>

#define S_DIM 128
#define R_DIM 256
#define CM    256
#define H_DIM 32
#define CZ    128
#define LN_EPS 1e-5f
#define EPS_N  1e-3f

// GEMM1 operands: [8192, 128] fp16, row-major (m=(i*32+h), k=s)
__device__ __half gAf[8192 * 128];
__device__ __half gBf[8192 * 128];
// w_out in mma-B-fragment order (see R11): 131072 uint32
__device__ uint32_t gWfrag[131072];
// w1/w2 in mma-B-fragment order: u = which*4096 + kt*256 + ntp*128 + lane*4 + r2
__device__ uint32_t gW12[8192];
__device__ float g_norm[R_DIM * R_DIM];

// ---------------------------------------------------------------------------
__device__ __forceinline__ uint32_t smem_u32(const void* p) {
    uint32_t a;
    asm("{ .reg .u64 t; cvta.to.shared.u64 t, %1; cvt.u32.u64 %0, t; }" : "=r"(a) : "l"(p));
    return a;
}
#define SWZ128(o) ((o) ^ (((o) >> 3) & 0x70))
#define CP_ASYNC16(dst, src) asm volatile("cp.async.cg.shared.global [%0], [%1], 16;" :: "r"(dst), "l"(src))
#define CP_COMMIT()          asm volatile("cp.async.commit_group;" ::: "memory")
#define CP_WAIT(n)           asm volatile("cp.async.wait_group %0;" :: "n"(n) : "memory")

__device__ __forceinline__ void ldsm_x4(uint32_t* r, uint32_t addr) {
    asm volatile("ldmatrix.sync.aligned.m8n8.x4.shared.b16 {%0,%1,%2,%3}, [%4];"
                 : "=r"(r[0]), "=r"(r[1]), "=r"(r[2]), "=r"(r[3]) : "r"(addr));
}
__device__ __forceinline__ void mma_f16(float* d, const uint32_t* a, const uint32_t* b) {
    asm volatile(
        "mma.sync.aligned.m16n8k16.row.col.f32.f16.f16.f32 "
        "{%0,%1,%2,%3}, {%4,%5,%6,%7}, {%8,%9}, {%0,%1,%2,%3};"
        : "+f"(d[0]), "+f"(d[1]), "+f"(d[2]), "+f"(d[3])
        : "r"(a[0]), "r"(a[1]), "r"(a[2]), "r"(a[3]),
          "r"(b[0]), "r"(b[1]));
}
__device__ __forceinline__ uint32_t pack_h2(float lo, float hi) {
    __half2 h;
    h.x = __float2half_rn(lo);
    h.y = __float2half_rn(hi);
    return *(uint32_t*)&h;
}

// ---------------------------------------------------------------------------
// Prep kernel (runs FIRST): gW12 packing, 32 blocks = which(2) x kt(16).
// Each block stages its 16x32 w slice (2 KB) and packs 256 fragment words.
// ---------------------------------------------------------------------------
__global__ void __launch_bounds__(256) prep_kernel(
    const float* __restrict__ w1, const float* __restrict__ w2)
{
    __shared__ float ws[16 * H_DIM];    // 2 KB
    const int which = blockIdx.x >> 4;
    const int kt = blockIdx.x & 15;
    const int t = threadIdx.x;
    const float* wsrc = which ? w2 : w1;

#pragma unroll
    for (int r = 0; r < 2; r++) {
        int idx = t + r * 256;          // 512 floats
        ws[idx] = wsrc[kt * 16 * H_DIM + idx];
    }
    __syncthreads();

    const int r2 = t & 3;
    const int lane = (t >> 2) & 31;
    const int ntp = (t >> 7) & 1;
    const int ntsub = r2 >> 1, rr = r2 & 1;
    const int k = (lane & 3) * 2 + rr * 8;            // local row in [0,16)
    const int n = (ntp * 2 + ntsub) * 8 + (lane >> 2);
    unsigned short lo = __half_as_ushort(__float2half_rn(ws[k * H_DIM + n]));
    unsigned short hi = __half_as_ushort(__float2half_rn(ws[(k + 1) * H_DIM + n]));
    gW12[which * 4096 + kt * 256 + t] = (uint32_t)lo | ((uint32_t)hi << 16);
}

// ---------------------------------------------------------------------------
// LN + projection kernel, 832 blocks (unchanged from R16):
//   [0,512):   LN + tensor-core projection (which=blk>>8, i=blk&255)
//   [512,768): norm matrix row i = blk-512
//   [768,832): gWfrag packing, ktg = blk-768
// Dynamic smem 74240 B.
// ---------------------------------------------------------------------------
__global__ void __launch_bounds__(256) lnproj_kernel(
    const float* __restrict__ m1, const float* __restrict__ mask1,
    const float* __restrict__ ln1w, const float* __restrict__ ln1b,
    const float* __restrict__ b1,
    const float* __restrict__ m2, const float* __restrict__ mask2,
    const float* __restrict__ ln2w, const float* __restrict__ ln2b,
    const float* __restrict__ b2,
    const float* __restrict__ w_out)
{
    extern __shared__ char psm[];
    const int blk = blockIdx.x;
    const int t = threadIdx.x;

    if (blk >= 768) {
        const int ktg = blk - 768;
        float* ws = (float*)psm;                  // [16][128]
#pragma unroll
        for (int r = 0; r < 8; r++) {
            int idx = t + r * 256;
            int kk = idx >> 7, n = idx & 127;
            ws[idx] = w_out[(ktg * 16 + kk) * CZ + n];
        }
        __syncthreads();
        const int lane = t & 31, ntp = t >> 5;
        uint32_t pk[4];
#pragma unroll
        for (int r2 = 0; r2 < 4; r2++) {
            int ntsub = r2 >> 1, rr = r2 & 1;
            int kk = (lane & 3) * 2 + rr * 8;
            int n = (ntp * 2 + ntsub) * 8 + (lane >> 2);
            pk[r2] = pack_h2(ws[kk * 128 + n], ws[(kk + 1) * 128 + n]);
        }
        *(uint4*)&gWfrag[ktg * 1024 + t * 4] = *(uint4*)pk;
        return;
    }
    if (blk >= 512) {
        const int i = blk - 512, j = t;
        float sum = 0.f;
#pragma unroll 4
        for (int s = 0; s < S_DIM; s++)
            sum += mask1[s * R_DIM + i] * mask2[s * R_DIM + j];
        g_norm[i * R_DIM + j] = sum + EPS_N;
        return;
    }

    const int which = blk >> 8;
    const int i = blk & 255;
    const float* m    = which ? m2 : m1;
    const float* mask = which ? mask2 : mask1;
    const float* lnw  = which ? ln2w : ln1w;
    const float* lnb  = which ? ln2b : ln1b;
    const float* bias = which ? b2 : b1;

    __half* xs = (__half*)psm;                 // [128][256] swizzled, 512 B rows
    __half* ts = (__half*)(psm + 65536);       // [32][136]
    const int w = t >> 5, lane = t & 31;
    const int quad = lane >> 3, r8 = lane & 7;

    const int c0 = lane * 8;
    float4 lw0 = *(const float4*)(lnw + c0);
    float4 lw1 = *(const float4*)(lnw + c0 + 4);
    float4 lb0 = *(const float4*)(lnb + c0);
    float4 lb1 = *(const float4*)(lnb + c0 + 4);
#pragma unroll 4
    for (int r = 0; r < 16; r++) {
        int s = w * 16 + r;
        const float* row = m + ((size_t)s * 256 + i) * CM;
        float4 v0 = *(const float4*)(row + c0);
        float4 v1 = *(const float4*)(row + c0 + 4);
        float sum = v0.x + v0.y + v0.z + v0.w + v1.x + v1.y + v1.z + v1.w;
#pragma unroll
        for (int o = 16; o; o >>= 1) sum += __shfl_xor_sync(0xffffffffu, sum, o);
        float mu = sum * (1.f / CM);
        float vs = (v0.x-mu)*(v0.x-mu) + (v0.y-mu)*(v0.y-mu) + (v0.z-mu)*(v0.z-mu)
                 + (v0.w-mu)*(v0.w-mu) + (v1.x-mu)*(v1.x-mu) + (v1.y-mu)*(v1.y-mu)
                 + (v1.z-mu)*(v1.z-mu) + (v1.w-mu)*(v1.w-mu);
#pragma unroll
        for (int o = 16; o; o >>= 1) vs += __shfl_xor_sync(0xffffffffu, vs, o);
        float rstd = rsqrtf(vs * (1.f / CM) + LN_EPS);
        uint4 pk;
        pk.x = pack_h2((v0.x - mu) * rstd * lw0.x + lb0.x,
                       (v0.y - mu) * rstd * lw0.y + lb0.y);
        pk.y = pack_h2((v0.z - mu) * rstd * lw0.z + lb0.z,
                       (v0.w - mu) * rstd * lw0.w + lb0.w);
        pk.z = pack_h2((v1.x - mu) * rstd * lw1.x + lb1.x,
                       (v1.y - mu) * rstd * lw1.y + lb1.y);
        pk.w = pack_h2((v1.z - mu) * rstd * lw1.z + lb1.z,
                       (v1.w - mu) * rstd * lw1.w + lb1.w);
        uint32_t off = (uint32_t)(s * 512 + ((lane * 16) ^ ((s & 7) << 4)));
        *(uint4*)((char*)xs + off) = pk;
    }
    __syncthreads();

    uint32_t sbx = smem_u32(xs);
    float acc[4][4];
#pragma unroll
    for (int a = 0; a < 4; a++)
#pragma unroll
        for (int b = 0; b < 4; b++) acc[a][b] = 0.f;

#pragma unroll
    for (int kt = 0; kt < 16; kt++) {
        int arow = w * 16 + (quad & 1) * 8 + r8;
        uint32_t akb = (uint32_t)(kt * 32 + (quad >> 1) * 16);
        uint32_t aoff = (uint32_t)(arow * 512) + (akb ^ ((uint32_t)(arow & 7) << 4));
        uint32_t a4[4];
        ldsm_x4(a4, sbx + aoff);
        uint4 wv0 = __ldg((const uint4*)gW12 + (which * 32 + kt * 2 + 0) * 32 + lane);
        uint4 wv1 = __ldg((const uint4*)gW12 + (which * 32 + kt * 2 + 1) * 32 + lane);
        uint32_t b0[2] = {wv0.x, wv0.y}, b1r[2] = {wv0.z, wv0.w};
        uint32_t b2r[2] = {wv1.x, wv1.y}, b3[2] = {wv1.z, wv1.w};
        mma_f16(acc[0], a4, b0);
        mma_f16(acc[1], a4, b1r);
        mma_f16(acc[2], a4, b2r);
        mma_f16(acc[3], a4, b3);
    }

    {
        float mk0 = mask[(w * 16 + (lane >> 2)) * 256 + i];
        float mk1 = mask[(w * 16 + (lane >> 2) + 8) * 256 + i];
#pragma unroll
        for (int n8 = 0; n8 < 4; n8++) {
            int h = n8 * 8 + (lane & 3) * 2;
            float bh0 = __ldg(bias + h), bh1 = __ldg(bias + h + 1);
#pragma unroll
            for (int hh = 0; hh < 2; hh++) {
                int s = w * 16 + (lane >> 2) + hh * 8;
                float mk = hh ? mk1 : mk0;
                ts[h * 136 + s]       = __float2half_rn((acc[n8][hh * 2 + 0] + bh0) * mk);
                ts[(h + 1) * 136 + s] = __float2half_rn((acc[n8][hh * 2 + 1] + bh1) * mk);
            }
        }
    }
    __syncthreads();

    {
        int h = t >> 3, g0 = t & 7;
        __half* dst = (which ? gBf : gAf);
#pragma unroll
        for (int r = 0; r < 2; r++) {
            int grp = g0 + r * 8;
            uint4 v = *(uint4*)((char*)ts + h * 272 + grp * 16);
            *(uint4*)&dst[((size_t)i * 32 + h) * 128 + grp * 8] = v;
        }
    }
}

// ---------------------------------------------------------------------------
// Mainloop blocks (fp16). K-chunk = 64 elems, SW128 tiles. 32 KB per chunk.
// ---------------------------------------------------------------------------
__device__ __forceinline__ void load_chunk_async(
    uint32_t sbuf, int m0, int n0, int k0, int t)
{
#pragma unroll
    for (int it = 0; it < 8; it++) {
        int id = it * 256 + t;
        int tile = id >> 10;
        int rem = id & 1023;
        int r = rem >> 3;
        int c8 = (rem & 7) * 8;
        const __half* src = (tile == 0)
            ? gAf + (size_t)(m0 + r) * 128 + k0 + c8
            : gBf + (size_t)(n0 + r) * 128 + k0 + c8;
        uint32_t off = (uint32_t)(r * 128 + c8 * 2);
        CP_ASYNC16(sbuf + tile * 16384 + SWZ128(off), src);
    }
}

__device__ __forceinline__ void compute_chunk(
    uint32_t sbuf, int wm0, int wn0, int lane, float (*acc)[4][4])
{
    const int quad = lane >> 3, r8 = lane & 7;
#pragma unroll
    for (int ks = 0; ks < 4; ks++) {
        const int kb = ks * 32;
        uint32_t a4[4][4];
#pragma unroll
        for (int mf = 0; mf < 4; mf++) {
            int row = wm0 + mf * 16 + (quad & 1) * 8 + r8;
            int kbyte = kb + (quad >> 1) * 16;
            ldsm_x4(a4[mf], sbuf + SWZ128((uint32_t)(row * 128 + kbyte)));
        }
        uint32_t b4[4][2];
#pragma unroll
        for (int nb = 0; nb < 2; nb++) {
            int row = wn0 + nb * 16 + (quad >> 1) * 8 + r8;
            int kbyte = kb + (quad & 1) * 16;
            uint32_t r4[4];
            ldsm_x4(r4, sbuf + 16384 + SWZ128((uint32_t)(row * 128 + kbyte)));
            b4[nb * 2][0] = r4[0]; b4[nb * 2][1] = r4[1];
            b4[nb * 2 + 1][0] = r4[2]; b4[nb * 2 + 1][1] = r4[3];
        }
#pragma unroll
        for (int mf = 0; mf < 4; mf++)
#pragma unroll
            for (int nf = 0; nf < 4; nf++)
                mma_f16(acc[mf][nf], a4[mf], b4[nf]);
    }
}

// ---------------------------------------------------------------------------
// Fused kernel. Dynamic smem 66560 B:
//   mainloop: chunk0 @0 (32 KB), chunk1 @32768 (32 KB)  [split-wait pipeline]
//   epilogue: O fp16 [16 p][1024 k] @0 (32 KB)
//             reduction slab @32768: [4 kp][16 p][132 floats] (33792 B)
// ---------------------------------------------------------------------------
__global__ void __launch_bounds__(256, 2) fused_kernel(
    const float* __restrict__ b_out, float* __restrict__ out)
{
    extern __shared__ char dsm[];
    const int t = threadIdx.x, wid = t >> 5, lane = t & 31;
    const int bi = blockIdx.y, bj = blockIdx.x;
    const int m0 = bi * 128, n0 = bj * 128;
    const int wm0 = (wid >> 2) * 64, wn0 = (wid & 3) * 32;
    const int quad = lane >> 3, r8 = lane & 7;
    uint32_t sb = smem_u32(dsm);

    float acc[4][4][4];
#pragma unroll
    for (int a = 0; a < 4; a++)
#pragma unroll
        for (int b = 0; b < 4; b++)
#pragma unroll
            for (int c = 0; c < 4; c++) acc[a][b][c] = 0.f;

    // ---- mainloop: split-wait double buffer ----
    load_chunk_async(sb, m0, n0, 0, t);
    CP_COMMIT();
    load_chunk_async(sb + 32768, m0, n0, 64, t);
    CP_COMMIT();
    CP_WAIT(1);
    __syncthreads();
    compute_chunk(sb, wm0, wn0, lane, acc);
    CP_WAIT(0);
    __syncthreads();
    compute_chunk(sb + 32768, wm0, wn0, lane, acc);

    // ---- stage outer tile to smem fp16: [p=16][k=1024] ----
    // (chunk0 region has no remaining readers: all warps passed the middle
    //  sync before compute_chunk(chunk1), which touches only [32K,64K).)
#pragma unroll
    for (int mf = 0; mf < 4; mf++)
#pragma unroll
        for (int nf = 0; nf < 4; nf++)
#pragma unroll
            for (int half = 0; half < 2; half++) {
                int gm = wm0 + mf * 16 + (lane >> 2) + half * 8;
                int gn = wn0 + nf * 8 + (lane & 3) * 2;
                int p = ((gm >> 5) << 2) | (gn >> 5);
                int k = ((gm & 31) << 5) | (gn & 31);
                __half2 hp;
                hp.x = __float2half_rn(acc[mf][nf][half * 2 + 0]);
                hp.y = __float2half_rn(acc[mf][nf][half * 2 + 1]);
                uint32_t off = (uint32_t)(p * 2048 + ((k * 2) ^ ((p & 7) << 4)));
                *(__half2*)(dsm + off) = hp;
            }
    __syncthreads();

    // ---- projection: warp (kp, np); k-slice 256, z-half 64 ----
    const int kp = wid & 3, np = wid >> 2;
    float zacc[8][4];
#pragma unroll
    for (int a = 0; a < 8; a++)
#pragma unroll
        for (int b = 0; b < 4; b++) zacc[a][b] = 0.f;

#pragma unroll
    for (int kt = 0; kt < 16; kt++) {
        int arow = (quad & 1) * 8 + r8;
        uint32_t akb = (uint32_t)(kp * 512 + kt * 32 + (quad >> 1) * 16);
        uint32_t aoff = (uint32_t)(arow * 2048) + (akb ^ ((uint32_t)(arow & 7) << 4));
        uint32_t ah[4];
        ldsm_x4(ah, sb + aoff);
        const int ktg = kp * 16 + kt;
        uint4 bv[4];
#pragma unroll
        for (int nl = 0; nl < 4; nl++)
            bv[nl] = __ldg(reinterpret_cast<const uint4*>(gWfrag)
                           + ((ktg * 8 + (np * 4 + nl)) * 32) + lane);
#pragma unroll
        for (int nl = 0; nl < 4; nl++) {
            uint32_t b0[2] = {bv[nl].x, bv[nl].y}, b1[2] = {bv[nl].z, bv[nl].w};
            mma_f16(zacc[nl * 2],     ah, b0);
            mma_f16(zacc[nl * 2 + 1], ah, b1);
        }
    }

    // ---- store partials: red[kp][p][132 floats]; np halves write disjoint z ----
    {
        char* red = dsm + 32768 + kp * 8448;
#pragma unroll
        for (int nf = 0; nf < 8; nf++)
#pragma unroll
            for (int hh = 0; hh < 2; hh++) {
                int p = (lane >> 2) + hh * 8;
                int z = np * 64 + nf * 8 + (lane & 3) * 2;
                float2 v;
                v.x = zacc[nf][hh * 2 + 0];
                v.y = zacc[nf][hh * 2 + 1];
                *(float2*)(red + p * 528 + z * 4) = v;
            }
    }
    __syncthreads();

    // ---- sum 4 partials, bias, 1/norm, store ----
#pragma unroll
    for (int g2 = 0; g2 < 2; g2++) {
        int cell = t + g2 * 256;
        int p = cell >> 5;
        int z = (cell & 31) * 4;
        float4 s = {0.f, 0.f, 0.f, 0.f};
#pragma unroll
        for (int w = 0; w < 4; w++) {
            float4 v = *(float4*)(dsm + 32768 + w * 8448 + p * 528 + z * 4);
            s.x += v.x; s.y += v.y; s.z += v.z; s.w += v.w;
        }
        int i = bi * 4 + (p >> 2), j = bj * 4 + (p & 3);
        float invn = 1.f / g_norm[i * R_DIM + j];
        float4 bo = __ldg((const float4*)(b_out + z));
        float4 o;
        o.x = (s.x + bo.x) * invn;
        o.y = (s.y + bo.y) * invn;
        o.z = (s.z + bo.z) * invn;
        o.w = (s.w + bo.w) * invn;
        *(float4*)(out + ((size_t)i * R_DIM + j) * CZ + z) = o;
    }
}

// ---------------------------------------------------------------------------
extern "C" void kernel_launch(void* const* d_in, const int* in_sizes, int n_in,
                              void* d_out, int out_size)
{
    const float* m_1    = (const float*)d_in[0];
    const float* m_2    = (const float*)d_in[1];
    const float* mask_1 = (const float*)d_in[2];
    const float* mask_2 = (const float*)d_in[3];
    const float* ln1_w  = (const float*)d_in[4];
    const float* ln1_b  = (const float*)d_in[5];
    const float* ln2_w  = (const float*)d_in[6];
    const float* ln2_b  = (const float*)d_in[7];
    const float* w1     = (const float*)d_in[8];
    const float* b1     = (const float*)d_in[9];
    const float* w2     = (const float*)d_in[10];
    const float* b2     = (const float*)d_in[11];
    const float* w_out  = (const float*)d_in[12];
    const float* b_out  = (const float*)d_in[13];
    float* out = (float*)d_out;

    cudaFuncSetAttribute(lnproj_kernel,
                         cudaFuncAttributeMaxDynamicSharedMemorySize, 74240);
    cudaFuncSetAttribute(fused_kernel,
                         cudaFuncAttributeMaxDynamicSharedMemorySize, 66560);

    prep_kernel<<<32, 256>>>(w1, w2);
    lnproj_kernel<<<832, 256, 74240>>>(m_1, mask_1, ln1_w, ln1_b, b1,
                                       m_2, mask_2, ln2_w, ln2_b, b2, w_out);
    fused_kernel<<<dim3(64, 64), 256, 66560>>>(b_out, out);
}